// round 11
// baseline (speedup 1.0000x reference)
#include <cuda_runtime.h>

// ---------------------------------------------------------------------------
// MultitaskSNN round 11: R10 frame (2 batches x half-neurons per thread,
// 224 thr x 147 blocks, halved SMEM weight traffic, spike-carry LIF) with a
// register diet:
//  1. exchange stores ONLY the partner's 7 spike pairs (28 regs vs R10's 56);
//     own pairs are consumed straight from ssA/ssB.
//  2. out layer uses compare-LIF (R9 form) -> no carried out-spikes (-8 regs).
// Per-neuron arithmetic order unchanged -> bit-exact vs reference.
// ---------------------------------------------------------------------------

typedef unsigned long long u64;
typedef unsigned int u32;

#define TT 50
#define NIN 32
#define THREADS 224

// u64-unit smem offsets
#define UW1  0      // [i=32][slot=16]: slots 0-6 h0 pairs, 8-14 h1 pairs
#define UB1  512    // [slot=16]
#define UW24 528    // [i=28][slot=16]: 0-6 h0 (class 4 + 3 pad), 8-14 h1 (reg 7)
#define UB24 976    // [slot=16]
#define UW5  992    // [i=14][slot=4]: 0={co0,co1} 1={co2,0} 2={ro,0} 3={0,0}
#define UB5  1048   // [slot=4]
#define SW_U64 1052

__device__ __forceinline__ u64 pack2(float lo, float hi) {
    u64 r; asm("mov.b64 %0, {%1, %2};" : "=l"(r) : "f"(lo), "f"(hi)); return r;
}
__device__ __forceinline__ void unpack2(u64 v, float& lo, float& hi) {
    asm("mov.b64 {%0, %1}, %2;" : "=f"(lo), "=f"(hi) : "l"(v));
}
__device__ __forceinline__ u64 fma2(u64 a, u64 b, u64 c) {
    u64 d; asm("fma.rn.f32x2 %0, %1, %2, %3;" : "=l"(d) : "l"(a), "l"(b), "l"(c)); return d;
}
__device__ __forceinline__ u64 add2(u64 a, u64 b) {
    u64 d; asm("add.rn.f32x2 %0, %1, %2;" : "=l"(d) : "l"(a), "l"(b)); return d;
}

#define BETA2  0x3F6666663F666666ull  // {0.9f, 0.9f}
#define NEG1X2 0xBF800000BF800000ull  // {-1.f, -1.f}

// spike-carry LIF: m = fma(s_prev, -1, fma(beta, m, cur)); s = (m > 1)
// Bit-exact: reset_t = spike(mem_{t-1}-1) == s_prev; fma(1,-1,z)=rn(z-1),
// fma(0,-1,z)=z.
__device__ __forceinline__ u64 lif2(u64& m2, u64 s2, u64 cur2) {
    m2 = fma2(s2, NEG1X2, fma2(BETA2, m2, cur2));
    float n0, n1;
    unpack2(m2, n0, n1);
    return pack2((n0 > 1.0f) ? 1.0f : 0.0f, (n1 > 1.0f) ? 1.0f : 0.0f);
}

// compare-LIF (no carried spike): r=(m>1)?-1:0; m=add(fma(beta,m,cur), r)
__device__ __forceinline__ void lif2c(u64& m2, u64 cur2) {
    float m0, m1;
    unpack2(m2, m0, m1);
    float r0 = (m0 > 1.0f) ? -1.0f : 0.0f;
    float r1 = (m1 > 1.0f) ? -1.0f : 0.0f;
    m2 = add2(fma2(BETA2, m2, cur2), pack2(r0, r1));
}

__global__ __launch_bounds__(THREADS, 1) void snn_kernel(
    const float* __restrict__ x,
    const float* __restrict__ Wsh, const float* __restrict__ bsh,
    const float* __restrict__ Wch, const float* __restrict__ bch,
    const float* __restrict__ Wco, const float* __restrict__ bco,
    const float* __restrict__ Wrh, const float* __restrict__ brh,
    const float* __restrict__ Wro, const float* __restrict__ bro,
    float* __restrict__ out, int B)
{
    __shared__ __align__(16) u64 swu[SW_U64];
    float* swf = (float*)swu;
    const int tid = threadIdx.x;

    for (int i = tid; i < SW_U64; i += THREADS) swu[i] = 0ull;
    __syncthreads();

    // L1 pairs: slot = 8h + pp holds {Wsh[14h+2pp][i], Wsh[14h+2pp+1][i]}
    for (int idx = tid; idx < 32 * 14; idx += THREADS) {
        int i = idx / 14, p = idx % 14, hh = p / 7, pp = p % 7;
        int o = 14 * hh + 2 * pp;
        int u = UW1 + i * 16 + 8 * hh + pp;
        swf[2 * u + 0] = Wsh[o * NIN + i];
        swf[2 * u + 1] = Wsh[(o + 1) * NIN + i];
    }
    for (int p = tid; p < 14; p += THREADS) {
        int hh = p / 7, pp = p % 7, o = 14 * hh + 2 * pp;
        swf[2 * (UB1 + 8 * hh + pp) + 0] = bsh[o];
        swf[2 * (UB1 + 8 * hh + pp) + 1] = bsh[o + 1];
    }
    // branch weights: class (h0, slots 0-3), reg (h1, slots 8-14)
    for (int idx = tid; idx < 8 * 28; idx += THREADS) {
        int o = idx / 28, i = idx % 28;
        swf[2 * (UW24 + i * 16 + (o >> 1)) + (o & 1)] = Wch[idx];
    }
    for (int idx = tid; idx < 14 * 28; idx += THREADS) {
        int o = idx / 28, i = idx % 28;
        swf[2 * (UW24 + i * 16 + 8 + (o >> 1)) + (o & 1)] = Wrh[idx];
    }
    for (int o = tid; o < 8; o += THREADS)
        swf[2 * (UB24 + (o >> 1)) + (o & 1)] = bch[o];
    for (int o = tid; o < 14; o += THREADS)
        swf[2 * (UB24 + 8 + (o >> 1)) + (o & 1)] = brh[o];
    // out layer
    for (int i = tid; i < 8; i += THREADS) {
        swf[2 * (UW5 + i * 4 + 0) + 0] = Wco[0 * 8 + i];
        swf[2 * (UW5 + i * 4 + 0) + 1] = Wco[1 * 8 + i];
        swf[2 * (UW5 + i * 4 + 1) + 0] = Wco[2 * 8 + i];
    }
    for (int i = tid; i < 14; i += THREADS)
        swf[2 * (UW5 + i * 4 + 2) + 0] = Wro[i];
    if (tid == 0) {
        swf[2 * (UB5 + 0) + 0] = bco[0];
        swf[2 * (UB5 + 0) + 1] = bco[1];
        swf[2 * (UB5 + 1) + 0] = bco[2];
        swf[2 * (UB5 + 2) + 0] = bro[0];
    }
    __syncthreads();

    const int gid = blockIdx.x * THREADS + tid;
    if (gid >= B) return;              // whole warps exit together
    const int h  = gid & 1;
    const int bA = gid & ~1;           // batch pair base (even)

    const u64* w1  = swu + UW1  + 8 * h;
    const u64* b1  = swu + UB1  + 8 * h;
    const u64* w24 = swu + UW24 + 8 * h;
    const u64* b24 = swu + UB24 + 8 * h;
    const u64* w5  = swu + UW5  + 2 * h;
    const u64* b5  = swu + UB5  + 2 * h;

    // membrane + carried-spike state (L1 and branch layers)
    u64 msA[7], msB[7], ssA[7], ssB[7];
    u64 mbA[7], mbB[7], sbA[7], sbB[7];
    u64 moA0 = 0ull, moA1 = 0ull, moB0 = 0ull, moB1 = 0ull;
#pragma unroll
    for (int p = 0; p < 7; p++) {
        msA[p] = 0ull; msB[p] = 0ull; ssA[p] = 0ull; ssB[p] = 0ull;
        mbA[p] = 0ull; mbB[p] = 0ull; sbA[p] = 0ull; sbB[p] = 0ull;
    }

    const size_t TB = (size_t)TT * B;
    float* p_mco = out;                 // [T,B,3]
    float* p_sch = out + TB * 3;        // [T,B,8]
    float* p_mro = out + TB * 11;       // [T,B,1]
    float* p_srh = out + TB * 12;       // [T,B,14]
    float* p_ssh = out + TB * 26;       // [T,B,28]

    const size_t xstep = (size_t)B * NIN;
    const float* xbase = x + (size_t)bA * NIN;

#pragma unroll 1
    for (int t = 0; t < TT; t++) {
        const float* xp = xbase + (size_t)t * xstep;
        if (t + 1 < TT) {
            asm volatile("prefetch.global.L2 [%0];" :: "l"(xp + xstep));
            asm volatile("prefetch.global.L2 [%0];" :: "l"(xp + xstep + NIN));
        }

        // ---- Layer 1: 7 neuron-pairs x 2 batches <- 32 inputs ----
        u64 aA[7], aB[7];
#pragma unroll
        for (int p = 0; p < 7; p++) { aA[p] = 0ull; aB[p] = 0ull; }
#pragma unroll
        for (int k = 0; k < 8; k++) {
            float4 a4 = __ldcs((const float4*)xp + k);
            float4 b4 = __ldcs((const float4*)(xp + NIN) + k);
            const float av[4] = {a4.x, a4.y, a4.z, a4.w};
            const float bv[4] = {b4.x, b4.y, b4.z, b4.w};
#pragma unroll
            for (int j = 0; j < 4; j++) {
                u64 dA = pack2(av[j], av[j]);
                u64 dB = pack2(bv[j], bv[j]);
                const u64* w = w1 + (4 * k + j) * 16;
                ulonglong2 w01 = *(const ulonglong2*)(w);
                ulonglong2 w23 = *(const ulonglong2*)(w + 2);
                ulonglong2 w45 = *(const ulonglong2*)(w + 4);
                u64 w6 = w[6];
                aA[0] = fma2(dA, w01.x, aA[0]); aB[0] = fma2(dB, w01.x, aB[0]);
                aA[1] = fma2(dA, w01.y, aA[1]); aB[1] = fma2(dB, w01.y, aB[1]);
                aA[2] = fma2(dA, w23.x, aA[2]); aB[2] = fma2(dB, w23.x, aB[2]);
                aA[3] = fma2(dA, w23.y, aA[3]); aB[3] = fma2(dB, w23.y, aB[3]);
                aA[4] = fma2(dA, w45.x, aA[4]); aB[4] = fma2(dB, w45.x, aB[4]);
                aA[5] = fma2(dA, w45.y, aA[5]); aB[5] = fma2(dB, w45.y, aB[5]);
                aA[6] = fma2(dA, w6,    aA[6]); aB[6] = fma2(dB, w6,    aB[6]);
            }
        }

        // LIF (spike-carry) + store spk_sh
#pragma unroll
        for (int p = 0; p < 7; p++) {
            ssA[p] = lif2(msA[p], ssA[p], add2(aA[p], b1[p]));
            ssB[p] = lif2(msB[p], ssB[p], add2(aB[p], b1[p]));
        }
        {
            float* pA = p_ssh + ((size_t)t * B + bA) * 28 + 14 * h;  // 8B aligned
            float* pB = pA + 28;
#pragma unroll
            for (int p = 0; p < 7; p++) {
                float a0, a1, b0, b1f;
                unpack2(ssA[p], a0, a1);
                unpack2(ssB[p], b0, b1f);
                __stcs((float2*)pA + p, make_float2(a0, a1));
                __stcs((float2*)pB + p, make_float2(b0, b1f));
            }
        }

        // ---- exchange: fetch ONLY the partner's 7 pairs (28 regs) ----
        u64 qA[7], qB[7];
#pragma unroll
        for (int p = 0; p < 7; p++) {
            qA[p] = __shfl_xor_sync(0xffffffffu, ssA[p], 1);
            qB[p] = __shfl_xor_sync(0xffffffffu, ssB[p], 1);
        }

        // ---- branch layer: 7 neuron-pairs x 2 batches <- 28 spikes ----
        // input pair pp: pp<7 -> global i = 2pp   (h0 own, h1 partner)
        //               pp>=7 -> global i = 2pp   (h0 partner, h1 own)
        u64 cA[7], cB[7];
#pragma unroll
        for (int p = 0; p < 7; p++) { cA[p] = 0ull; cB[p] = 0ull; }
#pragma unroll
        for (int pp = 0; pp < 14; pp++) {
            const int pl = (pp < 7) ? pp : pp - 7;
            u64 inA = (pp < 7) ? (h ? qA[pl] : ssA[pl]) : (h ? ssA[pl] : qA[pl]);
            u64 inB = (pp < 7) ? (h ? qB[pl] : ssB[pl]) : (h ? ssB[pl] : qB[pl]);
            float sa0, sa1, sb0, sb1;
            unpack2(inA, sa0, sa1);
            unpack2(inB, sb0, sb1);
#pragma unroll
            for (int half = 0; half < 2; half++) {
                const float sa = half ? sa1 : sa0;
                const float sb = half ? sb1 : sb0;
                const int i = 2 * pp + half;
                u64 dA = pack2(sa, sa);
                u64 dB = pack2(sb, sb);
                const u64* w = w24 + i * 16;
                ulonglong2 w01 = *(const ulonglong2*)(w);
                ulonglong2 w23 = *(const ulonglong2*)(w + 2);
                ulonglong2 w45 = *(const ulonglong2*)(w + 4);
                u64 w6 = w[6];
                cA[0] = fma2(dA, w01.x, cA[0]); cB[0] = fma2(dB, w01.x, cB[0]);
                cA[1] = fma2(dA, w01.y, cA[1]); cB[1] = fma2(dB, w01.y, cB[1]);
                cA[2] = fma2(dA, w23.x, cA[2]); cB[2] = fma2(dB, w23.x, cB[2]);
                cA[3] = fma2(dA, w23.y, cA[3]); cB[3] = fma2(dB, w23.y, cB[3]);
                cA[4] = fma2(dA, w45.x, cA[4]); cB[4] = fma2(dB, w45.x, cB[4]);
                cA[5] = fma2(dA, w45.y, cA[5]); cB[5] = fma2(dB, w45.y, cB[5]);
                cA[6] = fma2(dA, w6,    cA[6]); cB[6] = fma2(dB, w6,    cB[6]);
            }
        }
#pragma unroll
        for (int p = 0; p < 7; p++) {
            sbA[p] = lif2(mbA[p], sbA[p], add2(cA[p], b24[p]));
            sbB[p] = lif2(mbB[p], sbB[p], add2(cB[p], b24[p]));
        }

        // branch spike stores (divergent, small)
        if (h == 0) {
            float f0, f1, f2, f3, f4, f5, f6, f7;
            float* p = p_sch + ((size_t)t * B + bA) * 8;   // 32B aligned
            unpack2(sbA[0], f0, f1); unpack2(sbA[1], f2, f3);
            unpack2(sbA[2], f4, f5); unpack2(sbA[3], f6, f7);
            __stcs((float4*)p,     make_float4(f0, f1, f2, f3));
            __stcs((float4*)p + 1, make_float4(f4, f5, f6, f7));
            unpack2(sbB[0], f0, f1); unpack2(sbB[1], f2, f3);
            unpack2(sbB[2], f4, f5); unpack2(sbB[3], f6, f7);
            __stcs((float4*)p + 2, make_float4(f0, f1, f2, f3));
            __stcs((float4*)p + 3, make_float4(f4, f5, f6, f7));
        } else {
            float* p = p_srh + ((size_t)t * B + bA) * 14;  // 8B aligned
#pragma unroll
            for (int k = 0; k < 7; k++) {
                float a0, a1;
                unpack2(sbA[k], a0, a1);
                __stcs((float2*)p + k, make_float2(a0, a1));
            }
            float* q = p + 14;
#pragma unroll
            for (int k = 0; k < 7; k++) {
                float b0, b1f;
                unpack2(sbB[k], b0, b1f);
                __stcs((float2*)q + k, make_float2(b0, b1f));
            }
        }

        // ---- out layer: 2 output-pairs x 2 batches <- 14 own spikes ----
        u64 oA0 = 0ull, oA1 = 0ull, oB0 = 0ull, oB1 = 0ull;
#pragma unroll
        for (int pp = 0; pp < 7; pp++) {
            float sa0, sa1, sb0, sb1;
            unpack2(sbA[pp], sa0, sa1);
            unpack2(sbB[pp], sb0, sb1);
#pragma unroll
            for (int half = 0; half < 2; half++) {
                const float sa = half ? sa1 : sa0;
                const float sb = half ? sb1 : sb0;
                const int i = 2 * pp + half;
                u64 dA = pack2(sa, sa);
                u64 dB = pack2(sb, sb);
                ulonglong2 wp = *(const ulonglong2*)(w5 + i * 4);
                oA0 = fma2(dA, wp.x, oA0); oA1 = fma2(dA, wp.y, oA1);
                oB0 = fma2(dB, wp.x, oB0); oB1 = fma2(dB, wp.y, oB1);
            }
        }
        lif2c(moA0, add2(oA0, b5[0]));
        lif2c(moA1, add2(oA1, b5[1]));
        lif2c(moB0, add2(oB0, b5[0]));
        lif2c(moB1, add2(oB1, b5[1]));

        if (h == 0) {
            float a0, a1, a2, pd, b0, b1f, b2;
            unpack2(moA0, a0, a1); unpack2(moA1, a2, pd);
            unpack2(moB0, b0, b1f); unpack2(moB1, b2, pd);
            float* p = p_mco + ((size_t)t * B + bA) * 3;   // 8B aligned
            __stcs((float2*)p,     make_float2(a0, a1));
            __stcs((float2*)p + 1, make_float2(a2, b0));
            __stcs((float2*)p + 2, make_float2(b1f, b2));
        } else {
            float rA, rB, pd;
            unpack2(moA0, rA, pd);
            unpack2(moB0, rB, pd);
            __stcs((float2*)(p_mro + (size_t)t * B + bA), make_float2(rA, rB));
        }
    }
}

extern "C" void kernel_launch(void* const* d_in, const int* in_sizes, int n_in,
                              void* d_out, int out_size) {
    const float* x   = (const float*)d_in[0];
    const float* Wsh = (const float*)d_in[1];
    const float* bsh = (const float*)d_in[2];
    const float* Wch = (const float*)d_in[3];
    const float* bch = (const float*)d_in[4];
    const float* Wco = (const float*)d_in[5];
    const float* bco = (const float*)d_in[6];
    const float* Wrh = (const float*)d_in[7];
    const float* brh = (const float*)d_in[8];
    const float* Wro = (const float*)d_in[9];
    const float* bro = (const float*)d_in[10];

    const int B = in_sizes[0] / (TT * NIN);
    const int blocks = (B + THREADS - 1) / THREADS;   // threads == B

    snn_kernel<<<blocks, THREADS>>>(x, Wsh, bsh, Wch, bch, Wco, bco,
                                    Wrh, brh, Wro, bro, (float*)d_out, B);
}